// round 9
// baseline (speedup 1.0000x reference)
#include <cuda_runtime.h>
#include <math.h>

#define BB 4
#define NN 512
#define DD 1024
#define EE 8
#define HH 4096
#define RR 32            // candidate rows: (b in 0..3) x (n in 0..7)
#define OUT_ELEMS (BB*NN*DD)

#define S1_SPLITS 32     // stage1 d-splits (32 d each)
#define S2_SPLITS 128    // stage2 j-splits (32 j each)

typedef unsigned long long ull;

// ---------------- device scratch ----------------
__device__ float g_wt[EE*DD];                // transposed gate weights [e][d]
__device__ int   g_flag[RR];
__device__ float g_gate0[RR];
__device__ float g_gs[RR];
__device__ float g_hpart[S1_SPLITS*RR*HH];   // 16 MB
__device__ float g_h[RR*HH];
__device__ float g_opart[S2_SPLITS*RR*DD];   // 16 MB

// ---------------- packed fp32x2 helpers ----------------
__device__ __forceinline__ void fma2(ull& d, ull a, ull b) {
    asm("fma.rn.f32x2 %0, %1, %2, %0;" : "+l"(d) : "l"(a), "l"(b));
}
__device__ __forceinline__ void unpack2(ull v, float& lo, float& hi) {
    asm("mov.b64 {%0, %1}, %2;" : "=f"(lo), "=f"(hi) : "l"(v));
}

__device__ __forceinline__ int row_x_off(int r) {
    return ((r >> 3) * NN + (r & 7)) * DD;
}

// ---------------- kernel 1: init flags + transpose w_gate ----------------
__global__ void init_kernel(const float* __restrict__ w_gate) {
    int idx = blockIdx.x * blockDim.x + threadIdx.x;
    if (idx < EE * DD) {
        int e = idx & 7, d = idx >> 3;
        g_wt[e * DD + d] = w_gate[idx];
    }
    if (idx < RR) g_flag[idx] = 0;
}

// ---------------- kernel 2: gate logits, argmax, p(e=0) for n<8 ----------------
__global__ void gate_kernel(const float* __restrict__ x,
                            const float* __restrict__ b_gate) {
    int tok  = (blockIdx.x * blockDim.x + threadIdx.x) >> 5;
    int lane = threadIdx.x & 31;

    float acc[8];
#pragma unroll
    for (int e = 0; e < 8; e++) acc[e] = 0.f;

    const float4* xp = reinterpret_cast<const float4*>(x + (size_t)tok * DD) + lane;
#pragma unroll
    for (int i = 0; i < 8; i++) {
        int d4 = i * 32 + lane;
        float4 xv = xp[i * 32];
#pragma unroll
        for (int e = 0; e < 8; e++) {
            float4 wv = *reinterpret_cast<const float4*>(&g_wt[e * DD + d4 * 4]);
            acc[e] += xv.x * wv.x + xv.y * wv.y + xv.z * wv.z + xv.w * wv.w;
        }
    }
#pragma unroll
    for (int e = 0; e < 8; e++)
#pragma unroll
        for (int off = 16; off > 0; off >>= 1)
            acc[e] += __shfl_xor_sync(0xffffffffu, acc[e], off);

    if (lane == 0) {
        float l[8];
#pragma unroll
        for (int e = 0; e < 8; e++) l[e] = acc[e] + b_gate[e];
        int am = 0; float mx = l[0];
#pragma unroll
        for (int e = 1; e < 8; e++) if (l[e] > mx) { mx = l[e]; am = e; }
        int b = tok >> 9;
        int n = tok & 511;
        g_flag[b * 8 + am] = 1;          // benign race: writers all store 1
        if (n < 8) {
            float s = 0.f, p0 = 0.f;
#pragma unroll
            for (int e = 0; e < 8; e++) {
                float t = expf(l[e] - mx);
                s += t;
                if (e == 0) p0 = t;
            }
            g_gate0[b * 8 + n] = p0 / s;
        }
    }
}

// ---------------- kernel 3: gate scores + aux loss (1 warp) ----------------
__global__ void score_loss_kernel(float* __restrict__ out) {
    int i = threadIdx.x;                 // b = i>>3, n = i&7
    float m = g_flag[i] ? g_gate0[i] : 0.f;
    float s = m;
    s += __shfl_xor_sync(0xffffffffu, s, 8);
    s += __shfl_xor_sync(0xffffffffu, s, 16);
    float gs = m / (s + 1e-6f) * 4.0f;   // capacity = 4
    g_gs[i] = gs;

    float imp = gs;
    imp += __shfl_xor_sync(0xffffffffu, imp, 8);
    imp += __shfl_xor_sync(0xffffffffu, imp, 16);
    float ld = (float)g_flag[i];
    ld += __shfl_xor_sync(0xffffffffu, ld, 8);
    ld += __shfl_xor_sync(0xffffffffu, ld, 16);

    float s1 = (i < 8) ? imp       : 0.f;
    float s2 = (i < 8) ? imp * imp : 0.f;
    float s3 = (i < 8) ? ld        : 0.f;
    float s4 = (i < 8) ? ld * ld   : 0.f;
#pragma unroll
    for (int off = 16; off > 0; off >>= 1) {
        s1 += __shfl_xor_sync(0xffffffffu, s1, off);
        s2 += __shfl_xor_sync(0xffffffffu, s2, off);
        s3 += __shfl_xor_sync(0xffffffffu, s3, off);
        s4 += __shfl_xor_sync(0xffffffffu, s4, off);
    }
    if (i == 0) {
        const float NEL = (float)(NN * EE);
        float m1 = s1 / NEL;
        float v1 = (s2 - s1 * s1 / NEL) / (NEL - 1.f);
        float m2 = s3 / NEL;
        float v2 = (s4 - s3 * s3 / NEL) / (NEL - 1.f);
        out[OUT_ELEMS] = v1 / (m1 * m1 + 1e-10f) + v2 / (m2 * m2 + 1e-10f);
    }
}

// ---------------- kernel 4: stage1 GEMM  h_pre = x[32,1024] @ w1[0] ----------------
// grid (32 j-tiles of 128 cols, 32 d-splits of 32), 128 threads (4 warps).
// Warp w owns rows 8w..8w+7 — rows fully partitioned, NO duplicated w loads.
// w loaded as ulonglong2 (LDG.128 -> two f32x2 pairs, zero MOVs);
// x splatted in smem, read as ulonglong2 (LDS.128 serves 2 d's per row).
__global__ void __launch_bounds__(128) stage1_kernel(const float* __restrict__ x,
                                                     const float* __restrict__ w1) {
    __shared__ float2 xs[RR][32];        // splatted x tile, 8 KB
    int t = threadIdx.x;
    int jb = blockIdx.x * 128;
    int db = blockIdx.y * 32;

#pragma unroll
    for (int q = 0; q < 8; q++) {
        int idx = t + 128 * q;           // 1024 entries
        int row = idx >> 5, dd = idx & 31;
        float v = x[row_x_off(row) + db + dd];
        xs[row][dd] = make_float2(v, v);
    }
    __syncthreads();

    int lane = t & 31, w = t >> 5;
    int rbase = w * 8;

    ull acc[8][2];
#pragma unroll
    for (int r = 0; r < 8; r++) { acc[r][0] = 0ULL; acc[r][1] = 0ULL; }

    const float* wb = w1 + (size_t)db * HH + jb + lane * 4;
#pragma unroll 4
    for (int dp = 0; dp < 16; dp++) {
        ulonglong2 wv0 = *reinterpret_cast<const ulonglong2*>(wb + (size_t)(2 * dp) * HH);
        ulonglong2 wv1 = *reinterpret_cast<const ulonglong2*>(wb + (size_t)(2 * dp + 1) * HH);
#pragma unroll
        for (int r = 0; r < 8; r++) {
            ulonglong2 xv = *reinterpret_cast<const ulonglong2*>(&xs[rbase + r][2 * dp]);
            fma2(acc[r][0], xv.x, wv0.x);
            fma2(acc[r][1], xv.x, wv0.y);
            fma2(acc[r][0], xv.y, wv1.x);
            fma2(acc[r][1], xv.y, wv1.y);
        }
    }
#pragma unroll
    for (int r = 0; r < 8; r++) {
        ulonglong2 o; o.x = acc[r][0]; o.y = acc[r][1];
        size_t base = ((size_t)blockIdx.y * RR + rbase + r) * HH + jb + lane * 4;
        *reinterpret_cast<ulonglong2*>(&g_hpart[base]) = o;
    }
}

// ---------------- kernel 5: split-K reduce + bias + exact GELU (float4) ----------------
__global__ void gelu_kernel(const float* __restrict__ b1) {
    int f4 = blockIdx.x * blockDim.x + threadIdx.x;     // 0..32767
    int h = (f4 * 4) & 4095;
    float4 v = *reinterpret_cast<const float4*>(&b1[h]);
#pragma unroll
    for (int s = 0; s < S1_SPLITS; s++) {
        float4 p = *reinterpret_cast<const float4*>(&g_hpart[(size_t)s * (RR * HH) + f4 * 4]);
        v.x += p.x; v.y += p.y; v.z += p.z; v.w += p.w;
    }
    const float k = 0.70710678118654752440f;
    v.x = 0.5f * v.x * (1.0f + erff(v.x * k));
    v.y = 0.5f * v.y * (1.0f + erff(v.y * k));
    v.z = 0.5f * v.z * (1.0f + erff(v.z * k));
    v.w = 0.5f * v.w * (1.0f + erff(v.w * k));
    *reinterpret_cast<float4*>(&g_h[f4 * 4]) = v;
}

// ---------------- kernel 6: stage2 GEMM  o_pre = h[32,4096] @ w2[0] ----------------
// grid (8 d-tiles of 128 cols, 128 j-splits of 32), 128 threads (4 warps).
__global__ void __launch_bounds__(128) stage2_kernel(const float* __restrict__ w2) {
    __shared__ float2 hs[RR][32];        // 8 KB
    int t = threadIdx.x;
    int dbt = blockIdx.x * 128;
    int jb  = blockIdx.y * 32;

#pragma unroll
    for (int q = 0; q < 8; q++) {
        int idx = t + 128 * q;
        int row = idx >> 5, jj = idx & 31;
        float v = g_h[row * HH + jb + jj];
        hs[row][jj] = make_float2(v, v);
    }
    __syncthreads();

    int lane = t & 31, w = t >> 5;
    int rbase = w * 8;

    ull acc[8][2];
#pragma unroll
    for (int r = 0; r < 8; r++) { acc[r][0] = 0ULL; acc[r][1] = 0ULL; }

    const float* wb = w2 + (size_t)jb * DD + dbt + lane * 4;
#pragma unroll 4
    for (int jp = 0; jp < 16; jp++) {
        ulonglong2 wv0 = *reinterpret_cast<const ulonglong2*>(wb + (size_t)(2 * jp) * DD);
        ulonglong2 wv1 = *reinterpret_cast<const ulonglong2*>(wb + (size_t)(2 * jp + 1) * DD);
#pragma unroll
        for (int r = 0; r < 8; r++) {
            ulonglong2 hv = *reinterpret_cast<const ulonglong2*>(&hs[rbase + r][2 * jp]);
            fma2(acc[r][0], hv.x, wv0.x);
            fma2(acc[r][1], hv.x, wv0.y);
            fma2(acc[r][0], hv.y, wv1.x);
            fma2(acc[r][1], hv.y, wv1.y);
        }
    }
#pragma unroll
    for (int r = 0; r < 8; r++) {
        ulonglong2 o; o.x = acc[r][0]; o.y = acc[r][1];
        size_t base = ((size_t)blockIdx.y * RR + rbase + r) * DD + dbt + lane * 4;
        *reinterpret_cast<ulonglong2*>(&g_opart[base]) = o;
    }
}

// ---------------- kernel 7: reduce partials, add b2, scale, write (float4) ----------------
// grid (32 rows, 4 chunks of 256 cols), 256 threads; 4 split-groups of 32.
__global__ void final_kernel(const float* __restrict__ b2,
                             float* __restrict__ out) {
    __shared__ float4 part[256];
    int r = blockIdx.x;
    int cbase = blockIdx.y * 256;
    int t = threadIdx.x;
    int c4 = t & 63;
    int sg = t >> 6;

    float4 v = make_float4(0.f, 0.f, 0.f, 0.f);
#pragma unroll
    for (int s = 0; s < 32; s++) {
        int sp = sg * 32 + s;
        float4 p = *reinterpret_cast<const float4*>(
            &g_opart[((size_t)sp * RR + r) * DD + cbase + c4 * 4]);
        v.x += p.x; v.y += p.y; v.z += p.z; v.w += p.w;
    }
    part[t] = v;
    __syncthreads();
    if (t < 64) {
        float4 a = part[t], b = part[t + 64], c = part[t + 128], d = part[t + 192];
        float4 bias = *reinterpret_cast<const float4*>(&b2[cbase + t * 4]);
        float gs = g_gs[r];
        float4 o;
        o.x = gs * (a.x + b.x + c.x + d.x + bias.x);
        o.y = gs * (a.y + b.y + c.y + d.y + bias.y);
        o.z = gs * (a.z + b.z + c.z + d.z + bias.z);
        o.w = gs * (a.w + b.w + c.w + d.w + bias.w);
        *reinterpret_cast<float4*>(&out[row_x_off(r) + cbase + t * 4]) = o;
    }
}

// ---------------- launch ----------------
extern "C" void kernel_launch(void* const* d_in, const int* in_sizes, int n_in,
                              void* d_out, int out_size) {
    const float* x      = (const float*)d_in[0];
    const float* w_gate = (const float*)d_in[1];
    const float* b_gate = (const float*)d_in[2];
    const float* w1     = (const float*)d_in[3];
    const float* b1     = (const float*)d_in[4];
    const float* w2     = (const float*)d_in[5];
    const float* b2     = (const float*)d_in[6];
    float* out = (float*)d_out;

    cudaMemsetAsync(d_out, 0, (size_t)OUT_ELEMS * sizeof(float));

    init_kernel<<<32, 256>>>(w_gate);
    gate_kernel<<<256, 256>>>(x, b_gate);
    score_loss_kernel<<<1, 32>>>(out);
    stage1_kernel<<<dim3(32, S1_SPLITS), 128>>>(x, w1);
    gelu_kernel<<<128, 256>>>(b1);
    stage2_kernel<<<dim3(8, S2_SPLITS), 128>>>(w2);
    final_kernel<<<dim3(32, 4), 256>>>(b2, out);
}

// round 10
// speedup vs baseline: 1.3095x; 1.3095x over previous
#include <cuda_runtime.h>
#include <math.h>

#define BB 4
#define NN 512
#define DD 1024
#define EE 8
#define HH 4096
#define RR 32            // candidate rows: (b in 0..3) x (n in 0..7)
#define OUT_ELEMS (BB*NN*DD)

#define S1_SPLITS 32     // stage1 d-splits (32 d each)
#define S2_SPLITS 128    // stage2 j-splits (32 j each)

typedef unsigned long long ull;

// ---------------- device scratch ----------------
__device__ float g_wt[EE*DD];            // transposed gate weights [e][d]
__device__ int   g_flag[RR];
__device__ float g_gate0[RR];
__device__ float g_gs[RR];
__device__ float g_hacc[RR*HH];          // stage1 accumulator (512 KB, L2-resident)
__device__ float g_h[RR*HH];             // gelu(hacc)
__device__ float g_oacc[RR*DD];          // stage2 accumulator (128 KB)

// ---------------- packed fp32x2 + REDG helpers ----------------
__device__ __forceinline__ void fma2(ull& d, ull a, ull b) {
    asm("fma.rn.f32x2 %0, %1, %2, %0;" : "+l"(d) : "l"(a), "l"(b));
}
__device__ __forceinline__ void unpack2(ull v, float& lo, float& hi) {
    asm("mov.b64 {%0, %1}, %2;" : "=f"(lo), "=f"(hi) : "l"(v));
}
__device__ __forceinline__ void redg_add_v4(float* p, float a, float b, float c, float d) {
    asm volatile("red.global.add.v4.f32 [%0], {%1, %2, %3, %4};"
                 :: "l"(p), "f"(a), "f"(b), "f"(c), "f"(d) : "memory");
}

__device__ __forceinline__ int row_x_off(int r) {
    return ((r >> 3) * NN + (r & 7)) * DD;
}

// ---------------- kernel 1: init accumulators (bias-preloaded) + gate prep ----------------
// 512 blocks x 256 threads = 131072 threads
__global__ void init_kernel(const float* __restrict__ w_gate,
                            const float* __restrict__ b1,
                            const float* __restrict__ b2) {
    int idx = blockIdx.x * blockDim.x + threadIdx.x;
    g_hacc[idx] = b1[idx & (HH - 1)];                // all 131072 entries
    if (idx < RR * DD) g_oacc[idx] = b2[idx & (DD - 1)];
    if (idx < EE * DD) {
        int e = idx & 7, d = idx >> 3;
        g_wt[e * DD + d] = w_gate[idx];
    }
    if (idx < RR) g_flag[idx] = 0;
}

// ---------------- kernel 2: gate logits, argmax, p(e=0) for n<8 ----------------
__global__ void gate_kernel(const float* __restrict__ x,
                            const float* __restrict__ b_gate) {
    int tok  = (blockIdx.x * blockDim.x + threadIdx.x) >> 5;
    int lane = threadIdx.x & 31;

    float acc[8];
#pragma unroll
    for (int e = 0; e < 8; e++) acc[e] = 0.f;

    const float4* xp = reinterpret_cast<const float4*>(x + (size_t)tok * DD) + lane;
#pragma unroll
    for (int i = 0; i < 8; i++) {
        int d4 = i * 32 + lane;
        float4 xv = xp[i * 32];
#pragma unroll
        for (int e = 0; e < 8; e++) {
            float4 wv = *reinterpret_cast<const float4*>(&g_wt[e * DD + d4 * 4]);
            acc[e] += xv.x * wv.x + xv.y * wv.y + xv.z * wv.z + xv.w * wv.w;
        }
    }
#pragma unroll
    for (int e = 0; e < 8; e++)
#pragma unroll
        for (int off = 16; off > 0; off >>= 1)
            acc[e] += __shfl_xor_sync(0xffffffffu, acc[e], off);

    if (lane == 0) {
        float l[8];
#pragma unroll
        for (int e = 0; e < 8; e++) l[e] = acc[e] + b_gate[e];
        int am = 0; float mx = l[0];
#pragma unroll
        for (int e = 1; e < 8; e++) if (l[e] > mx) { mx = l[e]; am = e; }
        int b = tok >> 9;
        int n = tok & 511;
        g_flag[b * 8 + am] = 1;          // benign race: writers all store 1
        if (n < 8) {
            float s = 0.f, p0 = 0.f;
#pragma unroll
            for (int e = 0; e < 8; e++) {
                float t = expf(l[e] - mx);
                s += t;
                if (e == 0) p0 = t;
            }
            g_gate0[b * 8 + n] = p0 / s;
        }
    }
}

// ---------------- kernel 3: gate scores + aux loss (1 warp) ----------------
__global__ void score_loss_kernel(float* __restrict__ out) {
    int i = threadIdx.x;                 // b = i>>3, n = i&7
    float m = g_flag[i] ? g_gate0[i] : 0.f;
    float s = m;
    s += __shfl_xor_sync(0xffffffffu, s, 8);
    s += __shfl_xor_sync(0xffffffffu, s, 16);
    float gs = m / (s + 1e-6f) * 4.0f;   // capacity = 4
    g_gs[i] = gs;

    float imp = gs;
    imp += __shfl_xor_sync(0xffffffffu, imp, 8);
    imp += __shfl_xor_sync(0xffffffffu, imp, 16);
    float ld = (float)g_flag[i];
    ld += __shfl_xor_sync(0xffffffffu, ld, 8);
    ld += __shfl_xor_sync(0xffffffffu, ld, 16);

    float s1 = (i < 8) ? imp       : 0.f;
    float s2 = (i < 8) ? imp * imp : 0.f;
    float s3 = (i < 8) ? ld        : 0.f;
    float s4 = (i < 8) ? ld * ld   : 0.f;
#pragma unroll
    for (int off = 16; off > 0; off >>= 1) {
        s1 += __shfl_xor_sync(0xffffffffu, s1, off);
        s2 += __shfl_xor_sync(0xffffffffu, s2, off);
        s3 += __shfl_xor_sync(0xffffffffu, s3, off);
        s4 += __shfl_xor_sync(0xffffffffu, s4, off);
    }
    if (i == 0) {
        const float NEL = (float)(NN * EE);
        float m1 = s1 / NEL;
        float v1 = (s2 - s1 * s1 / NEL) / (NEL - 1.f);
        float m2 = s3 / NEL;
        float v2 = (s4 - s3 * s3 / NEL) / (NEL - 1.f);
        out[OUT_ELEMS] = v1 / (m1 * m1 + 1e-10f) + v2 / (m2 * m2 + 1e-10f);
    }
}

// ---------------- kernel 4: stage1 GEMM  hacc += x[32,1024] @ w1[0] ----------------
// grid (32 j-tiles of 128 cols, 32 d-splits of 32), 128 threads (4 warps).
// Warp w owns rows 8w..8w+7; results REDG.v4 into L2-resident g_hacc.
__global__ void __launch_bounds__(128) stage1_kernel(const float* __restrict__ x,
                                                     const float* __restrict__ w1) {
    __shared__ float2 xs[RR][32];        // splatted x tile, 8 KB
    int t = threadIdx.x;
    int jb = blockIdx.x * 128;
    int db = blockIdx.y * 32;

#pragma unroll
    for (int q = 0; q < 8; q++) {
        int idx = t + 128 * q;           // 1024 entries
        int row = idx >> 5, dd = idx & 31;
        float v = x[row_x_off(row) + db + dd];
        xs[row][dd] = make_float2(v, v);
    }
    __syncthreads();

    int lane = t & 31, w = t >> 5;
    int rbase = w * 8;

    ull acc[8][2];
#pragma unroll
    for (int r = 0; r < 8; r++) { acc[r][0] = 0ULL; acc[r][1] = 0ULL; }

    const float* wb = w1 + (size_t)db * HH + jb + lane * 4;
#pragma unroll 4
    for (int dp = 0; dp < 16; dp++) {
        ulonglong2 wv0 = *reinterpret_cast<const ulonglong2*>(wb + (size_t)(2 * dp) * HH);
        ulonglong2 wv1 = *reinterpret_cast<const ulonglong2*>(wb + (size_t)(2 * dp + 1) * HH);
#pragma unroll
        for (int r = 0; r < 8; r++) {
            ulonglong2 xv = *reinterpret_cast<const ulonglong2*>(&xs[rbase + r][2 * dp]);
            fma2(acc[r][0], xv.x, wv0.x);
            fma2(acc[r][1], xv.x, wv0.y);
            fma2(acc[r][0], xv.y, wv1.x);
            fma2(acc[r][1], xv.y, wv1.y);
        }
    }
#pragma unroll
    for (int r = 0; r < 8; r++) {
        float a, b, c, d;
        unpack2(acc[r][0], a, b);
        unpack2(acc[r][1], c, d);
        redg_add_v4(&g_hacc[(size_t)(rbase + r) * HH + jb + lane * 4], a, b, c, d);
    }
}

// ---------------- kernel 5: exact GELU on accumulator (tiny: 512 KB) ----------------
__global__ void gelu_kernel() {
    int f4 = blockIdx.x * blockDim.x + threadIdx.x;     // 0..32767
    float4 v = *reinterpret_cast<const float4*>(&g_hacc[f4 * 4]);
    const float k = 0.70710678118654752440f;
    v.x = 0.5f * v.x * (1.0f + erff(v.x * k));
    v.y = 0.5f * v.y * (1.0f + erff(v.y * k));
    v.z = 0.5f * v.z * (1.0f + erff(v.z * k));
    v.w = 0.5f * v.w * (1.0f + erff(v.w * k));
    *reinterpret_cast<float4*>(&g_h[f4 * 4]) = v;
}

// ---------------- kernel 6: stage2 GEMM  oacc += h[32,4096] @ w2[0] ----------------
// grid (8 d-tiles of 128 cols, 128 j-splits of 32), 128 threads (4 warps).
__global__ void __launch_bounds__(128) stage2_kernel(const float* __restrict__ w2) {
    __shared__ float2 hs[RR][32];        // 8 KB
    int t = threadIdx.x;
    int dbt = blockIdx.x * 128;
    int jb  = blockIdx.y * 32;

#pragma unroll
    for (int q = 0; q < 8; q++) {
        int idx = t + 128 * q;
        int row = idx >> 5, jj = idx & 31;
        float v = g_h[row * HH + jb + jj];
        hs[row][jj] = make_float2(v, v);
    }
    __syncthreads();

    int lane = t & 31, w = t >> 5;
    int rbase = w * 8;

    ull acc[8][2];
#pragma unroll
    for (int r = 0; r < 8; r++) { acc[r][0] = 0ULL; acc[r][1] = 0ULL; }

    const float* wb = w2 + (size_t)jb * DD + dbt + lane * 4;
#pragma unroll 4
    for (int jp = 0; jp < 16; jp++) {
        ulonglong2 wv0 = *reinterpret_cast<const ulonglong2*>(wb + (size_t)(2 * jp) * DD);
        ulonglong2 wv1 = *reinterpret_cast<const ulonglong2*>(wb + (size_t)(2 * jp + 1) * DD);
#pragma unroll
        for (int r = 0; r < 8; r++) {
            ulonglong2 hv = *reinterpret_cast<const ulonglong2*>(&hs[rbase + r][2 * jp]);
            fma2(acc[r][0], hv.x, wv0.x);
            fma2(acc[r][1], hv.x, wv0.y);
            fma2(acc[r][0], hv.y, wv1.x);
            fma2(acc[r][1], hv.y, wv1.y);
        }
    }
#pragma unroll
    for (int r = 0; r < 8; r++) {
        float a, b, c, d;
        unpack2(acc[r][0], a, b);
        unpack2(acc[r][1], c, d);
        redg_add_v4(&g_oacc[(size_t)(rbase + r) * DD + dbt + lane * 4], a, b, c, d);
    }
}

// ---------------- kernel 7: scale by gate, write out (tiny: 128 KB) ----------------
// grid 32 blocks (one per row) x 256 threads, one float4 each
__global__ void final_kernel(float* __restrict__ out) {
    int r = blockIdx.x;
    int t = threadIdx.x;
    float gs = g_gs[r];
    float4 v = *reinterpret_cast<const float4*>(&g_oacc[r * DD + t * 4]);
    float4 o;
    o.x = gs * v.x; o.y = gs * v.y; o.z = gs * v.z; o.w = gs * v.w;
    *reinterpret_cast<float4*>(&out[row_x_off(r) + t * 4]) = o;
}

// ---------------- launch ----------------
extern "C" void kernel_launch(void* const* d_in, const int* in_sizes, int n_in,
                              void* d_out, int out_size) {
    const float* x      = (const float*)d_in[0];
    const float* w_gate = (const float*)d_in[1];
    const float* b_gate = (const float*)d_in[2];
    const float* w1     = (const float*)d_in[3];
    const float* b1     = (const float*)d_in[4];
    const float* w2     = (const float*)d_in[5];
    const float* b2     = (const float*)d_in[6];
    float* out = (float*)d_out;

    cudaMemsetAsync(d_out, 0, (size_t)OUT_ELEMS * sizeof(float));

    init_kernel<<<512, 256>>>(w_gate, b1, b2);
    gate_kernel<<<256, 256>>>(x, b_gate);
    score_loss_kernel<<<1, 32>>>(out);
    stage1_kernel<<<dim3(32, S1_SPLITS), 128>>>(x, w1);
    gelu_kernel<<<128, 256>>>();
    stage2_kernel<<<dim3(8, S2_SPLITS), 128>>>(w2);
    final_kernel<<<32, 256>>>(out);
}

// round 14
// speedup vs baseline: 1.6574x; 1.2656x over previous
#include <cuda_runtime.h>
#include <math.h>

#define BB 4
#define NN 512
#define DD 1024
#define EE 8
#define HH 4096
#define RR 32            // candidate rows: (b in 0..3) x (n in 0..7)
#define OUT_ELEMS (BB*NN*DD)

#define S1_SPLITS 32     // stage1 d-splits (32 d each)
#define S2_SPLITS 128    // stage2 j-splits (32 j each)
#define S1_BLOCKS (32 * S1_SPLITS)          // 1024
#define S2_BLOCKS (8 * S2_SPLITS)           // 1024

typedef unsigned long long ull;

// ---------------- device scratch ----------------
__device__ float g_wt[EE*DD];            // transposed gate weights [e][d]
__device__ int   g_flag[RR];
__device__ float g_gate0[RR];
__device__ float g_gs[RR];
__device__ float g_hacc[RR*HH];          // stage1 accumulator (512 KB, L2-resident)
__device__ float g_oacc[RR*DD];          // stage2 accumulator (128 KB)

// ---------------- packed fp32x2 + REDG helpers ----------------
__device__ __forceinline__ void fma2(ull& d, ull a, ull b) {
    asm("fma.rn.f32x2 %0, %1, %2, %0;" : "+l"(d) : "l"(a), "l"(b));
}
__device__ __forceinline__ void unpack2(ull v, float& lo, float& hi) {
    asm("mov.b64 {%0, %1}, %2;" : "=f"(lo), "=f"(hi) : "l"(v));
}
__device__ __forceinline__ void redg_add_v4(float* p, float a, float b, float c, float d) {
    asm volatile("red.global.add.v4.f32 [%0], {%1, %2, %3, %4};"
                 :: "l"(p), "f"(a), "f"(b), "f"(c), "f"(d) : "memory");
}

__device__ __forceinline__ int row_x_off(int r) {
    return ((r >> 3) * NN + (r & 7)) * DD;
}

// ---------------- kernel 1: init accumulators (bias-preloaded) + gate prep ----------------
__global__ void init_kernel(const float* __restrict__ w_gate,
                            const float* __restrict__ b1,
                            const float* __restrict__ b2) {
    int idx = blockIdx.x * blockDim.x + threadIdx.x;   // 131072 threads
    g_hacc[idx] = b1[idx & (HH - 1)];
    if (idx < RR * DD) g_oacc[idx] = b2[idx & (DD - 1)];
    if (idx < EE * DD) {
        int e = idx & 7, d = idx >> 3;
        g_wt[e * DD + d] = w_gate[idx];
    }
    if (idx < RR) g_flag[idx] = 0;
}

// ---------------- gate block body (128 threads: 4 warps x 1 token) ----------------
__device__ void gate_block(const float* __restrict__ x,
                           const float* __restrict__ b_gate,
                           int gblk, int t) {
    int warp = t >> 5, lane = t & 31;
    int tok = gblk * 4 + warp;               // 512 gate blocks * 4 = 2048 tokens

    float acc[8];
#pragma unroll
    for (int e = 0; e < 8; e++) acc[e] = 0.f;

    const float4* xp = reinterpret_cast<const float4*>(x + (size_t)tok * DD) + lane;
#pragma unroll
    for (int i = 0; i < 8; i++) {
        int d4 = i * 32 + lane;
        float4 xv = xp[i * 32];
#pragma unroll
        for (int e = 0; e < 8; e++) {
            float4 wv = *reinterpret_cast<const float4*>(&g_wt[e * DD + d4 * 4]);
            acc[e] += xv.x * wv.x + xv.y * wv.y + xv.z * wv.z + xv.w * wv.w;
        }
    }
#pragma unroll
    for (int e = 0; e < 8; e++)
#pragma unroll
        for (int off = 16; off > 0; off >>= 1)
            acc[e] += __shfl_xor_sync(0xffffffffu, acc[e], off);

    if (lane == 0) {
        float l[8];
#pragma unroll
        for (int e = 0; e < 8; e++) l[e] = acc[e] + b_gate[e];
        int am = 0; float mx = l[0];
#pragma unroll
        for (int e = 1; e < 8; e++) if (l[e] > mx) { mx = l[e]; am = e; }
        int b = tok >> 9;
        int n = tok & 511;
        g_flag[b * 8 + am] = 1;              // benign race: writers all store 1
        if (n < 8) {
            float s = 0.f, p0 = 0.f;
#pragma unroll
            for (int e = 0; e < 8; e++) {
                float t2 = expf(l[e] - mx);
                s += t2;
                if (e == 0) p0 = t2;
            }
            g_gate0[b * 8 + n] = p0 / s;
        }
    }
}

// ---------------- kernel 2: stage1 GEMM (blocks 0..1023)  ⊕  gate (blocks 1024..1535) ----
// stage1: j-tile = blk & 31 (128 cols), d-split = blk >> 5 (32 d). 4 warps, 8 rows/warp.
// Depth-2 software pipeline on weight LDG.128.
__global__ void __launch_bounds__(128) stage1_gate_kernel(const float* __restrict__ x,
                                                          const float* __restrict__ w1,
                                                          const float* __restrict__ b_gate) {
    int blk = blockIdx.x;
    int t = threadIdx.x;
    if (blk >= S1_BLOCKS) {                  // ---- gate half ----
        gate_block(x, b_gate, blk - S1_BLOCKS, t);
        return;
    }

    __shared__ float2 xs[RR][32];            // splatted x tile, 8 KB
    int jb = (blk & 31) * 128;
    int db = (blk >> 5) * 32;

#pragma unroll
    for (int q = 0; q < 8; q++) {
        int idx = t + 128 * q;               // 1024 entries
        int row = idx >> 5, dd = idx & 31;
        float v = x[row_x_off(row) + db + dd];
        xs[row][dd] = make_float2(v, v);
    }
    __syncthreads();

    int lane = t & 31, w = t >> 5;
    int rbase = w * 8;

    ull acc[8][2];
#pragma unroll
    for (int r = 0; r < 8; r++) { acc[r][0] = 0ULL; acc[r][1] = 0ULL; }

    const float* wb = w1 + (size_t)db * HH + jb + lane * 4;
    ulonglong2 p0a = *reinterpret_cast<const ulonglong2*>(wb + 0 * HH);
    ulonglong2 p0b = *reinterpret_cast<const ulonglong2*>(wb + 1 * HH);
    ulonglong2 p1a = *reinterpret_cast<const ulonglong2*>(wb + 2 * HH);
    ulonglong2 p1b = *reinterpret_cast<const ulonglong2*>(wb + 3 * HH);

#pragma unroll 4
    for (int dp = 0; dp < 16; dp++) {
        ulonglong2 ca = p0a, cb = p0b;
        p0a = p1a; p0b = p1b;
        if (dp < 14) {
            p1a = *reinterpret_cast<const ulonglong2*>(wb + (size_t)(2 * dp + 4) * HH);
            p1b = *reinterpret_cast<const ulonglong2*>(wb + (size_t)(2 * dp + 5) * HH);
        }
#pragma unroll
        for (int r = 0; r < 8; r++) {
            ulonglong2 xv = *reinterpret_cast<const ulonglong2*>(&xs[rbase + r][2 * dp]);
            fma2(acc[r][0], xv.x, ca.x);
            fma2(acc[r][1], xv.x, ca.y);
            fma2(acc[r][0], xv.y, cb.x);
            fma2(acc[r][1], xv.y, cb.y);
        }
    }
#pragma unroll
    for (int r = 0; r < 8; r++) {
        float a, b, c, d;
        unpack2(acc[r][0], a, b);
        unpack2(acc[r][1], c, d);
        redg_add_v4(&g_hacc[(size_t)(rbase + r) * HH + jb + lane * 4], a, b, c, d);
    }
}

// ---------------- score_loss body (warp 0 of one block) ----------------
__device__ void score_loss_block(float* __restrict__ out, int i) {
    float m = g_flag[i] ? g_gate0[i] : 0.f;
    float s = m;
    s += __shfl_xor_sync(0xffffffffu, s, 8);
    s += __shfl_xor_sync(0xffffffffu, s, 16);
    float gs = m / (s + 1e-6f) * 4.0f;       // capacity = 4
    g_gs[i] = gs;

    float imp = gs;
    imp += __shfl_xor_sync(0xffffffffu, imp, 8);
    imp += __shfl_xor_sync(0xffffffffu, imp, 16);
    float ld = (float)g_flag[i];
    ld += __shfl_xor_sync(0xffffffffu, ld, 8);
    ld += __shfl_xor_sync(0xffffffffu, ld, 16);

    float s1 = (i < 8) ? imp       : 0.f;
    float s2 = (i < 8) ? imp * imp : 0.f;
    float s3 = (i < 8) ? ld        : 0.f;
    float s4 = (i < 8) ? ld * ld   : 0.f;
#pragma unroll
    for (int off = 16; off > 0; off >>= 1) {
        s1 += __shfl_xor_sync(0xffffffffu, s1, off);
        s2 += __shfl_xor_sync(0xffffffffu, s2, off);
        s3 += __shfl_xor_sync(0xffffffffu, s3, off);
        s4 += __shfl_xor_sync(0xffffffffu, s4, off);
    }
    if (i == 0) {
        const float NEL = (float)(NN * EE);
        float m1 = s1 / NEL;
        float v1 = (s2 - s1 * s1 / NEL) / (NEL - 1.f);
        float m2 = s3 / NEL;
        float v2 = (s4 - s3 * s3 / NEL) / (NEL - 1.f);
        out[OUT_ELEMS] = v1 / (m1 * m1 + 1e-10f) + v2 / (m2 * m2 + 1e-10f);
    }
}

// ---------------- kernel 3: stage2 GEMM (blocks 0..1023) ⊕ score_loss (block 1024) ------
// GELU applied inline during the smem fill.
__global__ void __launch_bounds__(128) stage2_loss_kernel(const float* __restrict__ w2,
                                                          float* __restrict__ out) {
    int blk = blockIdx.x;
    int t = threadIdx.x;
    if (blk >= S2_BLOCKS) {                  // ---- score/loss block ----
        if (t < 32) score_loss_block(out, t);
        return;
    }

    __shared__ float2 hs[RR][32];            // 8 KB
    int dbt = (blk & 7) * 128;
    int jb  = (blk >> 3) * 32;

    const float kgelu = 0.70710678118654752440f;
#pragma unroll
    for (int q = 0; q < 8; q++) {
        int idx = t + 128 * q;
        int row = idx >> 5, jj = idx & 31;
        float v = g_hacc[row * HH + jb + jj];
        v = 0.5f * v * (1.0f + erff(v * kgelu));
        hs[row][jj] = make_float2(v, v);
    }
    __syncthreads();

    int lane = t & 31, w = t >> 5;
    int rbase = w * 8;

    ull acc[8][2];
#pragma unroll
    for (int r = 0; r < 8; r++) { acc[r][0] = 0ULL; acc[r][1] = 0ULL; }

    const float* wb = w2 + (size_t)jb * DD + dbt + lane * 4;
    ulonglong2 p0a = *reinterpret_cast<const ulonglong2*>(wb + 0 * DD);
    ulonglong2 p0b = *reinterpret_cast<const ulonglong2*>(wb + 1 * DD);
    ulonglong2 p1a = *reinterpret_cast<const ulonglong2*>(wb + 2 * DD);
    ulonglong2 p1b = *reinterpret_cast<const ulonglong2*>(wb + 3 * DD);

#pragma unroll 4
    for (int jp = 0; jp < 16; jp++) {
        ulonglong2 ca = p0a, cb = p0b;
        p0a = p1a; p0b = p1b;
        if (jp < 14) {
            p1a = *reinterpret_cast<const ulonglong2*>(wb + (size_t)(2 * jp + 4) * DD);
            p1b = *reinterpret_cast<const ulonglong2*>(wb + (size_t)(2 * jp + 5) * DD);
        }
#pragma unroll
        for (int r = 0; r < 8; r++) {
            ulonglong2 hv = *reinterpret_cast<const ulonglong2*>(&hs[rbase + r][2 * jp]);
            fma2(acc[r][0], hv.x, ca.x);
            fma2(acc[r][1], hv.x, ca.y);
            fma2(acc[r][0], hv.y, cb.x);
            fma2(acc[r][1], hv.y, cb.y);
        }
    }
#pragma unroll
    for (int r = 0; r < 8; r++) {
        float a, b, c, d;
        unpack2(acc[r][0], a, b);
        unpack2(acc[r][1], c, d);
        redg_add_v4(&g_oacc[(size_t)(rbase + r) * DD + dbt + lane * 4], a, b, c, d);
    }
}

// ---------------- kernel 4: write FULL output (zeros + scaled candidate rows) ----------
// grid 2048 blocks (one per token) x 256 threads, one float4 each. Replaces memset.
__global__ void final_kernel(float* __restrict__ out) {
    int tok = blockIdx.x;                    // 0..2047
    int t = threadIdx.x;
    int n = tok & 511;
    float4 o = make_float4(0.f, 0.f, 0.f, 0.f);
    if (n < 8) {
        int r = (tok >> 9) * 8 + n;          // candidate row index
        float gs = g_gs[r];
        float4 v = *reinterpret_cast<const float4*>(&g_oacc[r * DD + t * 4]);
        o.x = gs * v.x; o.y = gs * v.y; o.z = gs * v.z; o.w = gs * v.w;
    }
    *reinterpret_cast<float4*>(&out[(size_t)tok * DD + t * 4]) = o;
}

// ---------------- launch (single stream, no allocations) ----------------
extern "C" void kernel_launch(void* const* d_in, const int* in_sizes, int n_in,
                              void* d_out, int out_size) {
    const float* x      = (const float*)d_in[0];
    const float* w_gate = (const float*)d_in[1];
    const float* b_gate = (const float*)d_in[2];
    const float* w1     = (const float*)d_in[3];
    const float* b1     = (const float*)d_in[4];
    const float* w2     = (const float*)d_in[5];
    const float* b2     = (const float*)d_in[6];
    float* out = (float*)d_out;

    init_kernel<<<512, 256>>>(w_gate, b1, b2);
    stage1_gate_kernel<<<S1_BLOCKS + 512, 128>>>(x, w1, b_gate);
    stage2_loss_kernel<<<S2_BLOCKS + 1, 128>>>(w2, out);
    final_kernel<<<BB * NN, 256>>>(out);
}